// round 12
// baseline (speedup 1.0000x reference)
#include <cuda_runtime.h>
#include <cstdint>

#define DI __device__ __forceinline__

// ---------------- problem sizes ----------------
#define B_ROWS   4096
#define IN_F     40960
#define HID      256
#define KC       64                 // fp32 K elems per chunk (2 x k32 IMMA steps)
#define NCHUNK   (IN_F / KC)        // 640
#define NBLK     128                // 64 M-tiles x 2 N-halves
#define TPB      512
#define WCHUNK_BYTES 32768          // full chunk (both N halves)
#define WHALF_BYTES  16384          // per-CTA half chunk

// A smem: two u8 digit planes (X1, X0), 128 rows x 64 bytes, row stride 80 (pad)
#define AROWB    80
#define APLANE   (128 * AROWB)      // 10240
#define ASTAGE   (2 * APLANE)       // 20480
#define SM_W0    0
#define SM_A0    (2 * WHALF_BYTES)  // 32768
#define DSMEM_BYTES (2 * WHALF_BYTES + 2 * ASTAGE + 1024)   // 74752

// ---------------- device scratch ----------------
// W digits fragment-interleaved:
// [chunk][nhalf(2)][ng(4)][(j*2+ks)*512 + lane*16] = {b0W1, b1W1, b0W0, b1W0}
__device__ __align__(128) uint8_t g_W[(size_t)NCHUNK * WCHUNK_BYTES];   // 20 MB
__device__ float  g_Sw[HID];        // per-column quant scale
__device__ double g_inv[HID];       // 1/(65535 * Sw[n])
__device__ float  g_x[(size_t)B_ROWS * 2 * HID];   // clipped concat [B, 512]

// ---------------- helpers ----------------
DI unsigned smem_u32(const void* p) {
    unsigned a;
    asm("{ .reg .u64 t; cvta.to.shared.u64 t, %1; cvt.u32.u64 %0, t; }" : "=r"(a) : "l"(p));
    return a;
}
DI unsigned lds32(unsigned a) {
    unsigned v;
    asm volatile("ld.shared.b32 %0, [%1];" : "=r"(v) : "r"(a));
    return v;
}
DI uint4 lds128(unsigned a) {
    uint4 v;
    asm volatile("ld.shared.v4.b32 {%0,%1,%2,%3}, [%4];"
                 : "=r"(v.x), "=r"(v.y), "=r"(v.z), "=r"(v.w) : "r"(a));
    return v;
}
DI void sts32(unsigned a, unsigned v) {
    asm volatile("st.shared.b32 [%0], %1;" :: "r"(a), "r"(v) : "memory");
}
DI void cp16(unsigned dst, const void* src) {
    asm volatile("cp.async.cg.shared.global [%0], [%1], 16;" :: "r"(dst), "l"(src) : "memory");
}
DI void cp_commit()  { asm volatile("cp.async.commit_group;" ::: "memory"); }
DI void cp_wait1()   { asm volatile("cp.async.wait_group 1;" ::: "memory"); }
DI void cp_wait0()   { asm volatile("cp.async.wait_group 0;" ::: "memory"); }

// D(s32) += A(u8, 16x32) * B(s8, 32x8)
DI void imma(int* d, unsigned a0, unsigned a1, unsigned a2, unsigned a3,
             unsigned b0, unsigned b1) {
    asm volatile(
        "mma.sync.aligned.m16n8k32.row.col.s32.u8.s8.s32 "
        "{%0,%1,%2,%3}, {%4,%5,%6,%7}, {%8,%9}, {%0,%1,%2,%3};"
        : "+r"(d[0]), "+r"(d[1]), "+r"(d[2]), "+r"(d[3])
        : "r"(a0), "r"(a1), "r"(a2), "r"(a3), "r"(b0), "r"(b1));
}

// ================= kernel 1a: per-column |W| max -> scales =================
__global__ void prep_scale_kernel(const float* __restrict__ Wft) {
    const int n   = blockIdx.x;          // 256 blocks
    const int tid = threadIdx.x;         // 256 threads
    const float* row = Wft + (size_t)n * IN_F;
    float m = 0.0f;
    for (int k = tid; k < IN_F; k += 256) m = fmaxf(m, fabsf(row[k]));
#pragma unroll
    for (int off = 16; off > 0; off >>= 1)
        m = fmaxf(m, __shfl_xor_sync(0xFFFFFFFFu, m, off));
    __shared__ float sm[8];
    if ((tid & 31) == 0) sm[tid >> 5] = m;
    __syncthreads();
    if (tid == 0) {
        float mm = sm[0];
#pragma unroll
        for (int i = 1; i < 8; i++) mm = fmaxf(mm, sm[i]);
        float Sw = 32639.0f / mm;
        g_Sw[n]  = Sw;
        g_inv[n] = 1.0 / (65535.0 * (double)Sw);
    }
}

// ================= kernel 1b: quantize W into digit fragments =================
// one thread per 16B unit: (chunk, nhalf, ng, j, ks, lane)
__global__ void prep_w_kernel(const float* __restrict__ Wft) {
    unsigned g     = blockIdx.x * 256u + threadIdx.x;   // NCHUNK*2048 threads
    unsigned lane  = g & 31u;
    unsigned ks    = (g >> 5) & 1u;
    unsigned j     = (g >> 6) & 3u;
    unsigned ng    = (g >> 8) & 3u;
    unsigned nhalf = (g >> 10) & 1u;
    unsigned c     = g >> 11;

    unsigned n = nhalf * 128u + ng * 32u + j * 8u + (lane >> 2);
    unsigned k = c * 64u + ks * 32u + (lane & 3u) * 4u;
    const float* src = Wft + (size_t)n * IN_F + k;
    float4 f0 = *(const float4*)(src);        // k .. k+3   -> b0
    float4 f1 = *(const float4*)(src + 16);   // k+16..k+19 -> b1
    float Sw = g_Sw[n];

    int W[8];
    W[0] = __float2int_rn(f0.x * Sw); W[1] = __float2int_rn(f0.y * Sw);
    W[2] = __float2int_rn(f0.z * Sw); W[3] = __float2int_rn(f0.w * Sw);
    W[4] = __float2int_rn(f1.x * Sw); W[5] = __float2int_rn(f1.y * Sw);
    W[6] = __float2int_rn(f1.z * Sw); W[7] = __float2int_rn(f1.w * Sw);

    unsigned w1b[8], w0b[8];
#pragma unroll
    for (int i = 0; i < 8; i++) {
        int hi = (W[i] + 128) >> 8;          // floor((W+128)/256)
        int lo = W[i] - (hi << 8);           // in [-128, 127]
        w1b[i] = (unsigned)hi & 255u;
        w0b[i] = (unsigned)lo & 255u;
    }
    uint4 v;
    v.x = w1b[0] | (w1b[1] << 8) | (w1b[2] << 16) | (w1b[3] << 24);   // b0 of W1
    v.y = w1b[4] | (w1b[5] << 8) | (w1b[6] << 16) | (w1b[7] << 24);   // b1 of W1
    v.z = w0b[0] | (w0b[1] << 8) | (w0b[2] << 16) | (w0b[3] << 24);   // b0 of W0
    v.w = w0b[4] | (w0b[5] << 8) | (w0b[6] << 16) | (w0b[7] << 24);   // b1 of W0
    *(uint4*)(g_W + (size_t)c * WCHUNK_BYTES + nhalf * WHALF_BYTES
              + ng * 4096u + (j * 2u + ks) * 512u + lane * 16u) = v;
}

// ================= kernel 2: feature-transformer GEMM (IMMA digit scheme) ======
// C[8192,256] = A @ W^T; CTA 128 rows x 128 cols, 16 warps, warp tile 32M x 32N
__global__ void __launch_bounds__(TPB, 1)
ft_gemm_kernel(const float* __restrict__ wfeat, const float* __restrict__ bfeat) {
    extern __shared__ uint8_t dsm[];
    const int tid = threadIdx.x;
    const int w   = tid >> 5;
    const int l   = tid & 31;
    const int b   = blockIdx.x;

    const int mtile = b >> 1;           // 0..63 (128 rows each)
    const int nhalf = b & 1;            // 0,1 (128 cols each)
    const bool white = (mtile < 32);
    const float* feat = white ? (wfeat + (size_t)mtile * 128 * IN_F)
                              : (bfeat + (size_t)(mtile - 32) * 128 * IN_F);

    const int mg = w >> 2;              // M group (0..3): rows mg*32..+31
    const int ng = w & 3;               // N group (0..3): cols ng*32..+31

    const unsigned sbase = (smem_u32(dsm) + 1023u) & ~1023u;
    const unsigned Wst[2] = { sbase + SM_W0, sbase + SM_W0 + WHALF_BYTES };
    const unsigned Ast[2] = { sbase + SM_A0, sbase + SM_A0 + ASTAGE };

    // A load mapping: li = i*512+tid -> row = i*32 + (tid>>4), fgroup = tid&15
    const float* abase = feat + (size_t)(tid >> 4) * IN_F + (unsigned)(tid & 15) * 4u;
    const unsigned stsbase = (unsigned)(tid >> 4) * AROWB + (unsigned)(tid & 15) * 4u;

    int accT2[2][4][4], accT1[2][4][4], accT0[2][4][4];
#pragma unroll
    for (int t = 0; t < 2; t++)
#pragma unroll
        for (int j = 0; j < 4; j++)
#pragma unroll
            for (int q = 0; q < 4; q++) {
                accT2[t][j][q] = 0; accT1[t][j][q] = 0; accT0[t][j][q] = 0;
            }

    // W copy: 512 threads x 2 x 16B = 16 KB per chunk (this CTA's N half)
    auto copyW = [&](int c, int st) {
        const uint8_t* src = g_W + (size_t)c * WCHUNK_BYTES
                             + (size_t)nhalf * WHALF_BYTES + tid * 16;
        unsigned dst = Wst[st] + tid * 16;
        cp16(dst, src);
        cp16(dst + 8192, src + 8192);
        cp_commit();
    };

    // quantize 16 floats -> u8 digit planes in stage st
    auto quantSTS = [&](const float4 av[4], int st) {
        unsigned p1 = Ast[st];            // X1 plane
        unsigned p0 = Ast[st] + APLANE;   // X0 plane
#pragma unroll
        for (int i = 0; i < 4; i++) {
            float4 f = av[i];
            unsigned X0 = __float2uint_rn(f.x * 65535.0f);
            unsigned X1 = __float2uint_rn(f.y * 65535.0f);
            unsigned X2 = __float2uint_rn(f.z * 65535.0f);
            unsigned X3 = __float2uint_rn(f.w * 65535.0f);
            unsigned hi = (X0 >> 8) | ((X1 >> 8) << 8) | ((X2 >> 8) << 16) | ((X3 >> 8) << 24);
            unsigned lo = (X0 & 255u) | ((X1 & 255u) << 8) | ((X2 & 255u) << 16) | ((X3 & 255u) << 24);
            unsigned off = stsbase + (unsigned)i * (32u * AROWB);
            sts32(p1 + off, hi);
            sts32(p0 + off, lo);
        }
    };

    // ---- prologue ----
    float4 av[4];
#pragma unroll
    for (int i = 0; i < 4; i++) av[i] = *(const float4*)(abase + (size_t)i * 32 * IN_F);
    quantSTS(av, 0);
    copyW(0, 0);
    copyW(1, 1);
    __syncthreads();

    const unsigned afrag0 = (unsigned)(mg * 32 + (l >> 2)) * AROWB + (unsigned)(l & 3) * 4u;

    for (int c = 0; c < NCHUNK; c++) {
        if (c + 1 < NCHUNK) {
#pragma unroll
            for (int i = 0; i < 4; i++)
                av[i] = *(const float4*)(abase + (size_t)i * 32 * IN_F + (size_t)(c + 1) * KC);
        }
        if (c + 1 < NCHUNK) cp_wait1(); else cp_wait0();
        __syncthreads();

        const unsigned aS = Ast[c & 1];
        const unsigned wS = Wst[c & 1] + (unsigned)ng * 4096u + (unsigned)l * 16u;

#pragma unroll
        for (int ks = 0; ks < 2; ks++) {
            unsigned aH[2][4], aL[2][4];   // X1 / X0 digit fragments per m-tile
#pragma unroll
            for (int t = 0; t < 2; t++) {
                unsigned base = aS + afrag0 + (unsigned)t * (16u * AROWB) + (unsigned)ks * 32u;
                aH[t][0] = lds32(base);
                aH[t][1] = lds32(base + 8u * AROWB);
                aH[t][2] = lds32(base + 16u);
                aH[t][3] = lds32(base + 8u * AROWB + 16u);
                aL[t][0] = lds32(base + APLANE);
                aL[t][1] = lds32(base + APLANE + 8u * AROWB);
                aL[t][2] = lds32(base + APLANE + 16u);
                aL[t][3] = lds32(base + APLANE + 8u * AROWB + 16u);
            }
#pragma unroll
            for (int j = 0; j < 4; j++) {
                uint4 bv = lds128(wS + (unsigned)(j * 2 + ks) * 512u);
#pragma unroll
                for (int t = 0; t < 2; t++) {
                    imma(accT2[t][j], aH[t][0], aH[t][1], aH[t][2], aH[t][3], bv.x, bv.y);
                    imma(accT1[t][j], aH[t][0], aH[t][1], aH[t][2], aH[t][3], bv.z, bv.w);
                    imma(accT1[t][j], aL[t][0], aL[t][1], aL[t][2], aL[t][3], bv.x, bv.y);
                    imma(accT0[t][j], aL[t][0], aL[t][1], aL[t][2], aL[t][3], bv.z, bv.w);
                }
            }
        }

        if (c + 1 < NCHUNK) quantSTS(av, (c + 1) & 1);
        __syncthreads();
        if (c + 2 < NCHUNK) copyW(c + 2, c & 1);
    }

    // ---- epilogue: reconstruct in double, clip, write concat g_x[B,512] ----
    const int rbase = (white ? mtile : mtile - 32) * 128 + mg * 32 + (l >> 2);
    float* xbase = g_x + (white ? 0 : HID);
#pragma unroll
    for (int t = 0; t < 2; t++) {
        const int r0 = rbase + t * 16;
#pragma unroll
        for (int j = 0; j < 4; j++) {
            const int col = nhalf * 128 + ng * 32 + j * 8 + (l & 3) * 2;
            double inv0 = g_inv[col], inv1 = g_inv[col + 1];
            double d0 = (65536.0 * (double)accT2[t][j][0] + 256.0 * (double)accT1[t][j][0]
                         + (double)accT0[t][j][0]) * inv0;
            double d1 = (65536.0 * (double)accT2[t][j][1] + 256.0 * (double)accT1[t][j][1]
                         + (double)accT0[t][j][1]) * inv1;
            double d2 = (65536.0 * (double)accT2[t][j][2] + 256.0 * (double)accT1[t][j][2]
                         + (double)accT0[t][j][2]) * inv0;
            double d3 = (65536.0 * (double)accT2[t][j][3] + 256.0 * (double)accT1[t][j][3]
                         + (double)accT0[t][j][3]) * inv1;
            float2 v0, v1;
            v0.x = fminf(fmaxf((float)d0, 0.0f), 1.0f);
            v0.y = fminf(fmaxf((float)d1, 0.0f), 1.0f);
            v1.x = fminf(fmaxf((float)d2, 0.0f), 1.0f);
            v1.y = fminf(fmaxf((float)d3, 0.0f), 1.0f);
            *(float2*)(xbase + (size_t)r0 * 512 + col)       = v0;
            *(float2*)(xbase + (size_t)(r0 + 8) * 512 + col) = v1;
        }
    }
}

// ================= kernel 3: MLP 512 -> 32 -> 32 -> 1 (warp per row) =================
__global__ void mlp_kernel(const float* __restrict__ W1, const float* __restrict__ b1,
                           const float* __restrict__ W2, const float* __restrict__ b2,
                           const float* __restrict__ W3, const float* __restrict__ b3,
                           const float* __restrict__ stm, float* __restrict__ out) {
    const int warp = (blockIdx.x * blockDim.x + threadIdx.x) >> 5;
    const int lid  = threadIdx.x & 31;
    if (warp >= B_ROWS) return;
    const float* xr = g_x + (size_t)warp * 512;

    float xv[16];
#pragma unroll
    for (int i = 0; i < 16; i++) xv[i] = xr[lid + 32 * i];

    float h1 = 0.0f;
#pragma unroll
    for (int j = 0; j < 32; j++) {
        const float* wrow = W1 + j * 512;
        float a = 0.0f;
#pragma unroll
        for (int i = 0; i < 16; i++) a += xv[i] * wrow[lid + 32 * i];
#pragma unroll
        for (int off = 16; off > 0; off >>= 1) a += __shfl_xor_sync(0xFFFFFFFFu, a, off);
        a = fmaxf(a + b1[j], 0.0f);
        if (lid == j) h1 = a;
    }

    float a2 = b2[lid];
#pragma unroll
    for (int k = 0; k < 32; k++)
        a2 += __shfl_sync(0xFFFFFFFFu, h1, k) * W2[lid * 32 + k];
    float h2 = fmaxf(a2, 0.0f);

    float v = h2 * W3[lid];
#pragma unroll
    for (int off = 16; off > 0; off >>= 1) v += __shfl_xor_sync(0xFFFFFFFFu, v, off);

    if (lid == 0) out[warp] = (v + b3[0]) * stm[warp];
}

// ================= host launcher =================
extern "C" void kernel_launch(void* const* d_in, const int* in_sizes, int n_in,
                              void* d_out, int out_size) {
    const float* wfeat = (const float*)d_in[0];
    const float* bfeat = (const float*)d_in[1];
    const float* stm   = (const float*)d_in[2];
    const float* Wft   = (const float*)d_in[3];
    const float* W1    = (const float*)d_in[4];
    const float* b1    = (const float*)d_in[5];
    const float* W2    = (const float*)d_in[6];
    const float* b2    = (const float*)d_in[7];
    const float* W3    = (const float*)d_in[8];
    const float* b3    = (const float*)d_in[9];

    static bool attr_set = false;
    if (!attr_set) {
        cudaFuncSetAttribute(ft_gemm_kernel,
                             cudaFuncAttributeMaxDynamicSharedMemorySize, DSMEM_BYTES);
        attr_set = true;
    }

    prep_scale_kernel<<<HID, 256>>>(Wft);
    prep_w_kernel<<<(NCHUNK * 2048) / 256, 256>>>(Wft);
    ft_gemm_kernel<<<NBLK, TPB, DSMEM_BYTES>>>(wfeat, bfeat);
    mlp_kernel<<<(B_ROWS * 32) / 256, 256>>>(W1, b1, W2, b2, W3, b3, stm, (float*)d_out);
}

// round 14
// speedup vs baseline: 3.6129x; 3.6129x over previous
#include <cuda_runtime.h>
#include <cuda_fp16.h>
#include <cstdint>

#define DI __device__ __forceinline__

// ---------------- problem sizes ----------------
#define B_ROWS   4096
#define IN_F     40960
#define HID      256
#define KC       64                 // fp32 K elems per chunk
#define NCHUNK   (IN_F / KC)        // 640
#define NBLK     128                // CTAs: 8192 rows / 64
#define TPB      256
#define WCHUNK_BYTES 65536          // W chunk: fragment-interleaved {wh,wl'}

// A smem staging: 64 rows x 144B (128B data + 16B pad) per hi / lo block
#define AROWB    144
#define ABLK     (64 * AROWB)       // 9216 bytes (one of hi/lo)
#define ASTAGE   (2 * ABLK)         // 18432 bytes
#define SM_W0    0
#define SM_A0    (2 * WCHUNK_BYTES) // 131072
#define DSMEM_BYTES (2 * WCHUNK_BYTES + 2 * ASTAGE + 1024)  // ~169 KB

#define LO_SCALE   2048.0f
#define INV_SCALE  (1.0f / 2048.0f)

// ---------------- device scratch ----------------
// W fragment-interleaved: [chunk][wng(4)][(j*4+s)*512 + lane*16] = {wh0,wh1,wl0,wl1}
__device__ __align__(128) uint8_t g_W[(size_t)NCHUNK * WCHUNK_BYTES];   // 40 MB
__device__ float g_x[(size_t)B_ROWS * 2 * HID];                         // clipped concat [B, 512]

// ---------------- helpers ----------------
DI unsigned smem_u32(const void* p) {
    unsigned a;
    asm("{ .reg .u64 t; cvta.to.shared.u64 t, %1; cvt.u32.u64 %0, t; }" : "=r"(a) : "l"(p));
    return a;
}
DI unsigned packh2(float lo, float hi) {
    __half2 v = __floats2half2_rn(lo, hi);
    return *(unsigned*)&v;
}
DI unsigned lds32(unsigned a) {
    unsigned v;
    asm volatile("ld.shared.b32 %0, [%1];" : "=r"(v) : "r"(a));
    return v;
}
DI uint4 lds128(unsigned a) {
    uint4 v;
    asm volatile("ld.shared.v4.b32 {%0,%1,%2,%3}, [%4];"
                 : "=r"(v.x), "=r"(v.y), "=r"(v.z), "=r"(v.w) : "r"(a));
    return v;
}
DI void sts64(unsigned a, unsigned x, unsigned y) {
    asm volatile("st.shared.v2.b32 [%0], {%1, %2};" :: "r"(a), "r"(x), "r"(y) : "memory");
}
DI void cp16(unsigned dst, const void* src) {
    asm volatile("cp.async.cg.shared.global [%0], [%1], 16;" :: "r"(dst), "l"(src) : "memory");
}
DI void cp_commit()  { asm volatile("cp.async.commit_group;" ::: "memory"); }
DI void cp_wait1()   { asm volatile("cp.async.wait_group 1;" ::: "memory"); }
DI void cp_wait0()   { asm volatile("cp.async.wait_group 0;" ::: "memory"); }

// fp16 x fp16 -> f32 accumulator
DI void mma_f32acc(float* d, unsigned a0, unsigned a1, unsigned a2, unsigned a3,
                   unsigned b0, unsigned b1) {
    asm volatile(
        "mma.sync.aligned.m16n8k16.row.col.f32.f16.f16.f32 "
        "{%0,%1,%2,%3}, {%4,%5,%6,%7}, {%8,%9}, {%0,%1,%2,%3};"
        : "+f"(d[0]), "+f"(d[1]), "+f"(d[2]), "+f"(d[3])
        : "r"(a0), "r"(a1), "r"(a2), "r"(a3), "r"(b0), "r"(b1));
}
// fp16 x fp16 -> f16 accumulator (2x rate hypothesis)
DI void mma_f16acc(unsigned* d, unsigned a0, unsigned a1, unsigned a2, unsigned a3,
                   unsigned b0, unsigned b1) {
    asm volatile(
        "mma.sync.aligned.m16n8k16.row.col.f16.f16.f16.f16 "
        "{%0,%1}, {%2,%3,%4,%5}, {%6,%7}, {%0,%1};"
        : "+r"(d[0]), "+r"(d[1])
        : "r"(a0), "r"(a1), "r"(a2), "r"(a3), "r"(b0), "r"(b1));
}

// ================= kernel 1: convert W_ft into fragment-interleaved fp16 hi/lo' ====
// one thread per 16B output unit: (chunk, wng, j, s, lane)
__global__ void prep_w_kernel(const float* __restrict__ Wft) {
    unsigned g    = blockIdx.x * 256u + threadIdx.x;   // NCHUNK*4096 threads
    unsigned lane = g & 31u;
    unsigned s    = (g >> 5) & 3u;
    unsigned j    = (g >> 7) & 7u;
    unsigned wg   = (g >> 10) & 3u;
    unsigned c    = g >> 12;

    unsigned n = wg * 64u + j * 8u + (lane >> 2);
    unsigned k = c * 64u + s * 16u + (lane & 3u) * 2u;
    const float* src = Wft + (size_t)n * IN_F + k;
    float w0 = src[0], w1 = src[1], w8 = src[8], w9 = src[9];

    __half h0 = __float2half_rn(w0), h1 = __float2half_rn(w1);
    __half h8 = __float2half_rn(w8), h9 = __float2half_rn(w9);
    float l0 = (w0 - __half2float(h0)) * LO_SCALE;
    float l1 = (w1 - __half2float(h1)) * LO_SCALE;
    float l8 = (w8 - __half2float(h8)) * LO_SCALE;
    float l9 = (w9 - __half2float(h9)) * LO_SCALE;

    uint4 v;
    {
        __half2 p0 = __halves2half2(h0, h1);
        __half2 p1 = __halves2half2(h8, h9);
        v.x = *(unsigned*)&p0;                 // wh pair (k, k+1)
        v.y = *(unsigned*)&p1;                 // wh pair (k+8, k+9)
    }
    v.z = packh2(l0, l1);                      // wl' pair (k, k+1)
    v.w = packh2(l8, l9);                      // wl' pair (k+8, k+9)
    *(uint4*)(g_W + (size_t)c * WCHUNK_BYTES + wg * 16384u + (j * 4u + s) * 512u + lane * 16u) = v;
}

// ================= kernel 2: feature-transformer GEMM (fp16, mixed accumulators) ===
// C[8192,256] = A @ W^T; CTA 64 rows x 256 cols, 8 warps, warp tile 32M x 64N
__global__ void __launch_bounds__(TPB, 1)
ft_gemm_kernel(const float* __restrict__ wfeat, const float* __restrict__ bfeat) {
    extern __shared__ uint8_t dsm[];
    const int tid = threadIdx.x;
    const int w   = tid >> 5;
    const int l   = tid & 31;
    const int b   = blockIdx.x;

    const bool white = (b < NBLK / 2);
    const float* feat = white ? (wfeat + (size_t)b * 64 * IN_F)
                              : (bfeat + (size_t)(b - NBLK / 2) * 64 * IN_F);

    const int mg  = w >> 2;             // M group (0,1)
    const int wng = w & 3;              // N group (0..3)

    const unsigned sbase = (smem_u32(dsm) + 1023u) & ~1023u;
    const unsigned Wst[2] = { sbase + SM_W0, sbase + SM_W0 + WCHUNK_BYTES };
    const unsigned Ast[2] = { sbase + SM_A0, sbase + SM_A0 + ASTAGE };

    // A coalesced load mapping: li = i*256+tid; row=li>>4, quad=li&15
    const float* aptr[4];
    unsigned stsoff[4];
#pragma unroll
    for (int i = 0; i < 4; i++) {
        unsigned li = (unsigned)(i * 256 + tid);
        aptr[i]   = feat + (size_t)(li >> 4) * IN_F + (li & 15u) * 4u;
        stsoff[i] = (li >> 4) * AROWB + (li & 15u) * 8u;
    }

    const unsigned aoff = (unsigned)(mg * 32 + (l >> 2)) * AROWB + (unsigned)(l & 3) * 4u;

    float    accM[2][8][4];   // main term (f32 accumulator MMAs)
    unsigned accC[2][8][2];   // cross terms (f16x2 accumulator MMAs), scaled by 2048
#pragma unroll
    for (int t = 0; t < 2; t++)
#pragma unroll
        for (int j = 0; j < 8; j++) {
#pragma unroll
            for (int q = 0; q < 4; q++) accM[t][j][q] = 0.0f;
            accC[t][j][0] = 0u; accC[t][j][1] = 0u;
        }

    // drain f16 cross accumulators into f32 main accumulators
    auto drain = [&]() {
#pragma unroll
        for (int t = 0; t < 2; t++)
#pragma unroll
            for (int j = 0; j < 8; j++) {
                float2 f0 = __half22float2(*(__half2*)&accC[t][j][0]);
                float2 f1 = __half22float2(*(__half2*)&accC[t][j][1]);
                accM[t][j][0] += f0.x * INV_SCALE;
                accM[t][j][1] += f0.y * INV_SCALE;
                accM[t][j][2] += f1.x * INV_SCALE;
                accM[t][j][3] += f1.y * INV_SCALE;
                accC[t][j][0] = 0u; accC[t][j][1] = 0u;
            }
    };

    // W copy: 256 threads x 16 x 16B = 64 KB per chunk
    auto copyW = [&](int c, int st) {
        const uint8_t* src = g_W + (size_t)c * WCHUNK_BYTES + tid * 16;
        unsigned dst = Wst[st] + tid * 16;
#pragma unroll
        for (int i = 0; i < 16; i++) cp16(dst + i * 4096, src + i * 4096);
        cp_commit();
    };

    // convert + STS one chunk of A (16 floats) into stage st: xh plane + xl' plane
    auto cvtSTS = [&](const float4 av[4], int st) {
        unsigned hi = Ast[st];
        unsigned lo = Ast[st] + ABLK;
#pragma unroll
        for (int i = 0; i < 4; i++) {
            float4 f = av[i];
            __half2 hA = __floats2half2_rn(f.x, f.y);
            __half2 hB = __floats2half2_rn(f.z, f.w);
            float lx = (f.x - __low2float(hA))  * LO_SCALE;
            float ly = (f.y - __high2float(hA)) * LO_SCALE;
            float lz = (f.z - __low2float(hB))  * LO_SCALE;
            float lw = (f.w - __high2float(hB)) * LO_SCALE;
            sts64(hi + stsoff[i], *(unsigned*)&hA, *(unsigned*)&hB);
            sts64(lo + stsoff[i], packh2(lx, ly), packh2(lz, lw));
        }
    };

    // ---- prologue ----
    float4 av[4];
#pragma unroll
    for (int i = 0; i < 4; i++) av[i] = *(const float4*)(aptr[i]);
    cvtSTS(av, 0);
    copyW(0, 0);
    copyW(1, 1);
    __syncthreads();

    for (int c = 0; c < NCHUNK; c++) {
        if (c + 1 < NCHUNK) {
#pragma unroll
            for (int i = 0; i < 4; i++)
                av[i] = *(const float4*)(aptr[i] + (size_t)(c + 1) * KC);
        }
        if (c + 1 < NCHUNK) cp_wait1(); else cp_wait0();
        __syncthreads();   // W(c) visible; A stage (c&1) ready

        const unsigned aS = Ast[c & 1];
        const unsigned wS = Wst[c & 1] + (unsigned)wng * 16384u + (unsigned)l * 16u;

#pragma unroll
        for (int s = 0; s < 4; s++) {
            unsigned ab = aS + aoff + (unsigned)s * 32u;
            unsigned ah[2][4], al[2][4];
#pragma unroll
            for (int t = 0; t < 2; t++) {
                unsigned base = ab + (unsigned)t * (16u * AROWB);
                ah[t][0] = lds32(base);
                ah[t][1] = lds32(base + 8u * AROWB);
                ah[t][2] = lds32(base + 16u);
                ah[t][3] = lds32(base + 8u * AROWB + 16u);
                al[t][0] = lds32(base + ABLK);
                al[t][1] = lds32(base + ABLK + 8u * AROWB);
                al[t][2] = lds32(base + ABLK + 16u);
                al[t][3] = lds32(base + ABLK + 8u * AROWB + 16u);
            }
            unsigned wb = wS + (unsigned)s * 512u;
#pragma unroll
            for (int j = 0; j < 8; j++) {
                uint4 bv = lds128(wb + (unsigned)j * 2048u);
#pragma unroll
                for (int t = 0; t < 2; t++) {
                    mma_f32acc(accM[t][j], ah[t][0], ah[t][1], ah[t][2], ah[t][3], bv.x, bv.y); // xh*wh
                    mma_f16acc(accC[t][j], al[t][0], al[t][1], al[t][2], al[t][3], bv.x, bv.y); // xl'*wh
                    mma_f16acc(accC[t][j], ah[t][0], ah[t][1], ah[t][2], ah[t][3], bv.z, bv.w); // xh*wl'
                }
            }
        }

        if ((c & 31) == 31) drain();   // bound f16 accumulator rounding (20 drains)

        if (c + 1 < NCHUNK) cvtSTS(av, (c + 1) & 1);
        __syncthreads();
        if (c + 2 < NCHUNK) copyW(c + 2, c & 1);
    }

    // ---- epilogue: clip to [0,1], write concat layout g_x[B,512] ----
    const int rbase = (white ? b : b - NBLK / 2) * 64 + mg * 32 + (l >> 2);
    float* xbase = g_x + (white ? 0 : HID);
#pragma unroll
    for (int t = 0; t < 2; t++) {
        const int r0 = rbase + t * 16;
#pragma unroll
        for (int j = 0; j < 8; j++) {
            const int col = wng * 64 + j * 8 + (l & 3) * 2;
            float2 v0, v1;
            v0.x = fminf(fmaxf(accM[t][j][0], 0.0f), 1.0f);
            v0.y = fminf(fmaxf(accM[t][j][1], 0.0f), 1.0f);
            v1.x = fminf(fmaxf(accM[t][j][2], 0.0f), 1.0f);
            v1.y = fminf(fmaxf(accM[t][j][3], 0.0f), 1.0f);
            *(float2*)(xbase + (size_t)r0 * 512 + col)       = v0;
            *(float2*)(xbase + (size_t)(r0 + 8) * 512 + col) = v1;
        }
    }
}

// ================= kernel 3: MLP 512 -> 32 -> 32 -> 1 (warp per row) =================
__global__ void mlp_kernel(const float* __restrict__ W1, const float* __restrict__ b1,
                           const float* __restrict__ W2, const float* __restrict__ b2,
                           const float* __restrict__ W3, const float* __restrict__ b3,
                           const float* __restrict__ stm, float* __restrict__ out) {
    const int warp = (blockIdx.x * blockDim.x + threadIdx.x) >> 5;
    const int lid  = threadIdx.x & 31;
    if (warp >= B_ROWS) return;
    const float* xr = g_x + (size_t)warp * 512;

    float xv[16];
#pragma unroll
    for (int i = 0; i < 16; i++) xv[i] = xr[lid + 32 * i];

    float h1 = 0.0f;
#pragma unroll
    for (int j = 0; j < 32; j++) {
        const float* wrow = W1 + j * 512;
        float a = 0.0f;
#pragma unroll
        for (int i = 0; i < 16; i++) a += xv[i] * wrow[lid + 32 * i];
#pragma unroll
        for (int off = 16; off > 0; off >>= 1) a += __shfl_xor_sync(0xFFFFFFFFu, a, off);
        a = fmaxf(a + b1[j], 0.0f);
        if (lid == j) h1 = a;
    }

    float a2 = b2[lid];
#pragma unroll
    for (int k = 0; k < 32; k++)
        a2 += __shfl_sync(0xFFFFFFFFu, h1, k) * W2[lid * 32 + k];
    float h2 = fmaxf(a2, 0.0f);

    float v = h2 * W3[lid];
#pragma unroll
    for (int off = 16; off > 0; off >>= 1) v += __shfl_xor_sync(0xFFFFFFFFu, v, off);

    if (lid == 0) out[warp] = (v + b3[0]) * stm[warp];
}

// ================= host launcher =================
extern "C" void kernel_launch(void* const* d_in, const int* in_sizes, int n_in,
                              void* d_out, int out_size) {
    const float* wfeat = (const float*)d_in[0];
    const float* bfeat = (const float*)d_in[1];
    const float* stm   = (const float*)d_in[2];
    const float* Wft   = (const float*)d_in[3];
    const float* W1    = (const float*)d_in[4];
    const float* b1    = (const float*)d_in[5];
    const float* W2    = (const float*)d_in[6];
    const float* b2    = (const float*)d_in[7];
    const float* W3    = (const float*)d_in[8];
    const float* b3    = (const float*)d_in[9];

    static bool attr_set = false;
    if (!attr_set) {
        cudaFuncSetAttribute(ft_gemm_kernel,
                             cudaFuncAttributeMaxDynamicSharedMemorySize, DSMEM_BYTES);
        attr_set = true;
    }

    prep_w_kernel<<<(NCHUNK * 4096) / 256, 256>>>(Wft);
    ft_gemm_kernel<<<NBLK, TPB, DSMEM_BYTES>>>(wfeat, bfeat);
    mlp_kernel<<<(B_ROWS * 32) / 256, 256>>>(W1, b1, W2, b2, W3, b3, stm, (float*)d_out);
}

// round 16
// speedup vs baseline: 4.1429x; 1.1467x over previous
#include <cuda_runtime.h>
#include <cuda_fp16.h>
#include <cstdint>

#define DI __device__ __forceinline__

// ---------------- problem sizes ----------------
#define B_ROWS   4096
#define IN_F     40960
#define HID      256
#define KC       64                 // fp32 K elems per chunk
#define NCHUNK   (IN_F / KC)        // 640 chunks total per row
#define KSPLIT   8
#define NCHUNK_U (NCHUNK / KSPLIT)  // 80 chunks per unit
#define KUNIT    (IN_F / KSPLIT)    // 5120 fp32 elems per unit
#define MTILES   128                // 8192 rows / 64
#define NUNITS   (MTILES * KSPLIT)  // 1024
#define GRIDP    152                // persistent CTAs (GB300: 152 SMs)
#define TPB      256
#define WCHUNK_BYTES 65536          // W chunk: fragment-interleaved {wh,wl'}

// A smem staging: 64 rows x 144B (128B data + 16B pad) per hi / lo block
#define AROWB    144
#define ABLK     (64 * AROWB)       // 9216 bytes
#define ASTAGE   (2 * ABLK)         // 18432 bytes
#define SM_W0    0
#define SM_A0    (2 * WCHUNK_BYTES) // 131072
#define DSMEM_BYTES (2 * WCHUNK_BYTES + 2 * ASTAGE + 1024)  // ~169 KB

#define LO_SCALE   2048.0f
#define INV_SCALE  (1.0f / 2048.0f)

// ---------------- device scratch ----------------
// W fragment-interleaved: [chunk][wng(4)][(j*4+s)*512 + lane*16] = {wh0,wh1,wl0,wl1}
__device__ __align__(128) uint8_t g_W[(size_t)NCHUNK * WCHUNK_BYTES];   // 40 MB
__device__ float g_part[(size_t)KSPLIT * 8192 * HID];                   // 64 MB partials
__device__ float g_x[(size_t)B_ROWS * 2 * HID];                         // clipped concat

// ---------------- helpers ----------------
DI unsigned smem_u32(const void* p) {
    unsigned a;
    asm("{ .reg .u64 t; cvta.to.shared.u64 t, %1; cvt.u32.u64 %0, t; }" : "=r"(a) : "l"(p));
    return a;
}
DI unsigned packh2(float lo, float hi) {
    __half2 v = __floats2half2_rn(lo, hi);
    return *(unsigned*)&v;
}
DI unsigned lds32(unsigned a) {
    unsigned v;
    asm volatile("ld.shared.b32 %0, [%1];" : "=r"(v) : "r"(a));
    return v;
}
DI uint4 lds128(unsigned a) {
    uint4 v;
    asm volatile("ld.shared.v4.b32 {%0,%1,%2,%3}, [%4];"
                 : "=r"(v.x), "=r"(v.y), "=r"(v.z), "=r"(v.w) : "r"(a));
    return v;
}
DI void sts64(unsigned a, unsigned x, unsigned y) {
    asm volatile("st.shared.v2.b32 [%0], {%1, %2};" :: "r"(a), "r"(x), "r"(y) : "memory");
}
DI void cp16(unsigned dst, const void* src) {
    asm volatile("cp.async.cg.shared.global [%0], [%1], 16;" :: "r"(dst), "l"(src) : "memory");
}
DI void cp_commit()  { asm volatile("cp.async.commit_group;" ::: "memory"); }
DI void cp_wait1()   { asm volatile("cp.async.wait_group 1;" ::: "memory"); }
DI void cp_wait0()   { asm volatile("cp.async.wait_group 0;" ::: "memory"); }

DI void mma_f32acc(float* d, unsigned a0, unsigned a1, unsigned a2, unsigned a3,
                   unsigned b0, unsigned b1) {
    asm volatile(
        "mma.sync.aligned.m16n8k16.row.col.f32.f16.f16.f32 "
        "{%0,%1,%2,%3}, {%4,%5,%6,%7}, {%8,%9}, {%0,%1,%2,%3};"
        : "+f"(d[0]), "+f"(d[1]), "+f"(d[2]), "+f"(d[3])
        : "r"(a0), "r"(a1), "r"(a2), "r"(a3), "r"(b0), "r"(b1));
}

// ================= kernel 1: convert W_ft into fragment-interleaved fp16 hi/lo' ====
__global__ void prep_w_kernel(const float* __restrict__ Wft) {
    unsigned g    = blockIdx.x * 256u + threadIdx.x;   // NCHUNK*4096 threads
    unsigned lane = g & 31u;
    unsigned s    = (g >> 5) & 3u;
    unsigned j    = (g >> 7) & 7u;
    unsigned wg   = (g >> 10) & 3u;
    unsigned c    = g >> 12;

    unsigned n = wg * 64u + j * 8u + (lane >> 2);
    unsigned k = c * 64u + s * 16u + (lane & 3u) * 2u;
    const float* src = Wft + (size_t)n * IN_F + k;
    float w0 = src[0], w1 = src[1], w8 = src[8], w9 = src[9];

    __half h0 = __float2half_rn(w0), h1 = __float2half_rn(w1);
    __half h8 = __float2half_rn(w8), h9 = __float2half_rn(w9);
    float l0 = (w0 - __half2float(h0)) * LO_SCALE;
    float l1 = (w1 - __half2float(h1)) * LO_SCALE;
    float l8 = (w8 - __half2float(h8)) * LO_SCALE;
    float l9 = (w9 - __half2float(h9)) * LO_SCALE;

    uint4 v;
    {
        __half2 p0 = __halves2half2(h0, h1);
        __half2 p1 = __halves2half2(h8, h9);
        v.x = *(unsigned*)&p0;
        v.y = *(unsigned*)&p1;
    }
    v.z = packh2(l0, l1);
    v.w = packh2(l8, l9);
    *(uint4*)(g_W + (size_t)c * WCHUNK_BYTES + wg * 16384u + (j * 4u + s) * 512u + lane * 16u) = v;
}

// ================= kernel 2: persistent FT GEMM (fp16 3-term, f32 accs) ===========
// 152 persistent CTAs; unit u = (mtile, kpart); static schedule u = bid + 152*i
__global__ void __launch_bounds__(TPB, 1)
ft_gemm_kernel(const float* __restrict__ wfeat, const float* __restrict__ bfeat) {
    extern __shared__ uint8_t dsm[];
    const int tid = threadIdx.x;
    const int w   = tid >> 5;
    const int l   = tid & 31;

    const int mg  = w >> 2;             // M group (0,1)
    const int wng = w & 3;              // N group (0..3)

    const unsigned sbase = (smem_u32(dsm) + 1023u) & ~1023u;
    const unsigned Wst[2] = { sbase + SM_W0, sbase + SM_W0 + WCHUNK_BYTES };
    const unsigned Ast[2] = { sbase + SM_A0, sbase + SM_A0 + ASTAGE };

    const unsigned aoff = (unsigned)(mg * 32 + (l >> 2)) * AROWB + (unsigned)(l & 3) * 4u;

    // A coalesced-load STS offsets (fixed across units)
    unsigned stsoff[4];
#pragma unroll
    for (int i = 0; i < 4; i++) {
        unsigned li = (unsigned)(i * 256 + tid);
        stsoff[i] = (li >> 4) * AROWB + (li & 15u) * 8u;
    }

    for (int u = blockIdx.x; u < NUNITS; u += GRIDP) {
        const int mtile = u >> 3;       // 0..127
        const int kpart = u & 7;        // 0..7
        const bool white = (mtile < 64);
        const float* feat = white ? (wfeat + (size_t)mtile * 64 * IN_F)
                                  : (bfeat + (size_t)(mtile - 64) * 64 * IN_F);
        const int cbase = kpart * NCHUNK_U;

        // per-unit A row pointers
        const float* aptr[4];
#pragma unroll
        for (int i = 0; i < 4; i++) {
            unsigned li = (unsigned)(i * 256 + tid);
            aptr[i] = feat + (size_t)(li >> 4) * IN_F + (li & 15u) * 4u + (size_t)kpart * KUNIT;
        }

        float accM[2][8][4];   // xh*wh
        float accC[2][8][4];   // 2048*(xl*wh + xh*wl)
#pragma unroll
        for (int t = 0; t < 2; t++)
#pragma unroll
            for (int j = 0; j < 8; j++)
#pragma unroll
                for (int q = 0; q < 4; q++) { accM[t][j][q] = 0.0f; accC[t][j][q] = 0.0f; }

        auto copyW = [&](int c, int st) {
            const uint8_t* src = g_W + (size_t)c * WCHUNK_BYTES + tid * 16;
            unsigned dst = Wst[st] + tid * 16;
#pragma unroll
            for (int i = 0; i < 16; i++) cp16(dst + i * 4096, src + i * 4096);
            cp_commit();
        };

        auto cvtSTS = [&](const float4 av[4], int st) {
            unsigned hi = Ast[st];
            unsigned lo = Ast[st] + ABLK;
#pragma unroll
            for (int i = 0; i < 4; i++) {
                float4 f = av[i];
                __half2 hA = __floats2half2_rn(f.x, f.y);
                __half2 hB = __floats2half2_rn(f.z, f.w);
                float lx = (f.x - __low2float(hA))  * LO_SCALE;
                float ly = (f.y - __high2float(hA)) * LO_SCALE;
                float lz = (f.z - __low2float(hB))  * LO_SCALE;
                float lw = (f.w - __high2float(hB)) * LO_SCALE;
                sts64(hi + stsoff[i], *(unsigned*)&hA, *(unsigned*)&hB);
                sts64(lo + stsoff[i], packh2(lx, ly), packh2(lz, lw));
            }
        };

        // ---- unit prologue ----
        float4 av[4];
#pragma unroll
        for (int i = 0; i < 4; i++) av[i] = *(const float4*)(aptr[i]);
        cvtSTS(av, 0);
        copyW(cbase + 0, 0);
        copyW(cbase + 1, 1);
        __syncthreads();

        for (int c = 0; c < NCHUNK_U; c++) {
            if (c + 1 < NCHUNK_U) {
#pragma unroll
                for (int i = 0; i < 4; i++)
                    av[i] = *(const float4*)(aptr[i] + (size_t)(c + 1) * KC);
            }
            if (c + 1 < NCHUNK_U) cp_wait1(); else cp_wait0();
            __syncthreads();

            const unsigned aS = Ast[c & 1];
            const unsigned wS = Wst[c & 1] + (unsigned)wng * 16384u + (unsigned)l * 16u;

#pragma unroll
            for (int s = 0; s < 4; s++) {
                unsigned ab = aS + aoff + (unsigned)s * 32u;
                unsigned ah[2][4], al[2][4];
#pragma unroll
                for (int t = 0; t < 2; t++) {
                    unsigned base = ab + (unsigned)t * (16u * AROWB);
                    ah[t][0] = lds32(base);
                    ah[t][1] = lds32(base + 8u * AROWB);
                    ah[t][2] = lds32(base + 16u);
                    ah[t][3] = lds32(base + 8u * AROWB + 16u);
                    al[t][0] = lds32(base + ABLK);
                    al[t][1] = lds32(base + ABLK + 8u * AROWB);
                    al[t][2] = lds32(base + ABLK + 16u);
                    al[t][3] = lds32(base + ABLK + 8u * AROWB + 16u);
                }
                unsigned wb = wS + (unsigned)s * 512u;
#pragma unroll
                for (int j = 0; j < 8; j++) {
                    uint4 bv = lds128(wb + (unsigned)j * 2048u);
#pragma unroll
                    for (int t = 0; t < 2; t++) {
                        mma_f32acc(accM[t][j], ah[t][0], ah[t][1], ah[t][2], ah[t][3], bv.x, bv.y);
                        mma_f32acc(accC[t][j], al[t][0], al[t][1], al[t][2], al[t][3], bv.x, bv.y);
                        mma_f32acc(accC[t][j], ah[t][0], ah[t][1], ah[t][2], ah[t][3], bv.z, bv.w);
                    }
                }
            }

            if (c + 1 < NCHUNK_U) cvtSTS(av, (c + 1) & 1);
            __syncthreads();
            if (c + 2 < NCHUNK_U) copyW(cbase + c + 2, c & 1);
        }

        // ---- unit epilogue: write raw partials ----
        float* pbase = g_part + (size_t)kpart * (8192 * HID);
        const int rbase = mtile * 64 + mg * 32 + (l >> 2);
#pragma unroll
        for (int t = 0; t < 2; t++) {
            const int r0 = rbase + t * 16;
#pragma unroll
            for (int j = 0; j < 8; j++) {
                const int col = wng * 64 + j * 8 + (l & 3) * 2;
                float2 v0, v1;
                v0.x = accM[t][j][0] + accC[t][j][0] * INV_SCALE;
                v0.y = accM[t][j][1] + accC[t][j][1] * INV_SCALE;
                v1.x = accM[t][j][2] + accC[t][j][2] * INV_SCALE;
                v1.y = accM[t][j][3] + accC[t][j][3] * INV_SCALE;
                *(float2*)(pbase + (size_t)r0 * HID + col)       = v0;
                *(float2*)(pbase + (size_t)(r0 + 8) * HID + col) = v1;
            }
        }
    }
}

// ================= kernel 3: combine partials, clip, concat =================
__global__ void combine_kernel() {
    unsigned idx = blockIdx.x * 256u + threadIdx.x;   // over 8192*256/4 float4s
    float4 s = make_float4(0.f, 0.f, 0.f, 0.f);
#pragma unroll
    for (int p = 0; p < KSPLIT; p++) {
        const float4 v = *(const float4*)(g_part + (size_t)p * (8192 * HID) + (size_t)idx * 4);
        s.x += v.x; s.y += v.y; s.z += v.z; s.w += v.w;
    }
    s.x = fminf(fmaxf(s.x, 0.f), 1.f);
    s.y = fminf(fmaxf(s.y, 0.f), 1.f);
    s.z = fminf(fmaxf(s.z, 0.f), 1.f);
    s.w = fminf(fmaxf(s.w, 0.f), 1.f);
    unsigned e = idx * 4;
    unsigned row = e >> 8;
    unsigned col = e & 255u;
    float* dst = (row < B_ROWS) ? (g_x + (size_t)row * 512 + col)
                                : (g_x + (size_t)(row - B_ROWS) * 512 + 256 + col);
    *(float4*)dst = s;
}

// ================= kernel 4: MLP 512 -> 32 -> 32 -> 1 (warp per row) =================
__global__ void mlp_kernel(const float* __restrict__ W1, const float* __restrict__ b1,
                           const float* __restrict__ W2, const float* __restrict__ b2,
                           const float* __restrict__ W3, const float* __restrict__ b3,
                           const float* __restrict__ stm, float* __restrict__ out) {
    const int warp = (blockIdx.x * blockDim.x + threadIdx.x) >> 5;
    const int lid  = threadIdx.x & 31;
    if (warp >= B_ROWS) return;
    const float* xr = g_x + (size_t)warp * 512;

    float xv[16];
#pragma unroll
    for (int i = 0; i < 16; i++) xv[i] = xr[lid + 32 * i];

    float h1 = 0.0f;
#pragma unroll
    for (int j = 0; j < 32; j++) {
        const float* wrow = W1 + j * 512;
        float a = 0.0f;
#pragma unroll
        for (int i = 0; i < 16; i++) a += xv[i] * wrow[lid + 32 * i];
#pragma unroll
        for (int off = 16; off > 0; off >>= 1) a += __shfl_xor_sync(0xFFFFFFFFu, a, off);
        a = fmaxf(a + b1[j], 0.0f);
        if (lid == j) h1 = a;
    }

    float a2 = b2[lid];
#pragma unroll
    for (int k = 0; k < 32; k++)
        a2 += __shfl_sync(0xFFFFFFFFu, h1, k) * W2[lid * 32 + k];
    float h2 = fmaxf(a2, 0.0f);

    float v = h2 * W3[lid];
#pragma unroll
    for (int off = 16; off > 0; off >>= 1) v += __shfl_xor_sync(0xFFFFFFFFu, v, off);

    if (lid == 0) out[warp] = (v + b3[0]) * stm[warp];
}

// ================= host launcher =================
extern "C" void kernel_launch(void* const* d_in, const int* in_sizes, int n_in,
                              void* d_out, int out_size) {
    const float* wfeat = (const float*)d_in[0];
    const float* bfeat = (const float*)d_in[1];
    const float* stm   = (const float*)d_in[2];
    const float* Wft   = (const float*)d_in[3];
    const float* W1    = (const float*)d_in[4];
    const float* b1    = (const float*)d_in[5];
    const float* W2    = (const float*)d_in[6];
    const float* b2    = (const float*)d_in[7];
    const float* W3    = (const float*)d_in[8];
    const float* b3    = (const float*)d_in[9];

    static bool attr_set = false;
    if (!attr_set) {
        cudaFuncSetAttribute(ft_gemm_kernel,
                             cudaFuncAttributeMaxDynamicSharedMemorySize, DSMEM_BYTES);
        attr_set = true;
    }

    prep_w_kernel<<<(NCHUNK * 4096) / 256, 256>>>(Wft);
    ft_gemm_kernel<<<GRIDP, TPB, DSMEM_BYTES>>>(wfeat, bfeat);
    combine_kernel<<<(8192 * HID / 4) / 256, 256>>>();
    mlp_kernel<<<(B_ROWS * 32) / 256, 256>>>(W1, b1, W2, b2, W3, b3, stm, (float*)d_out);
}